// round 1
// baseline (speedup 1.0000x reference)
#include <cuda_runtime.h>
#include <math.h>

#define DM   1024
#define DH   64
#define NH   16
#define SEQ  2048
#define NB   2
#define MTOT (NB*SEQ)   // 4096
#define LDP  68         // padded smem stride (float4-aligned: 68*4=272=17*16)

// Scratch (allocation-free rule: __device__ globals)
__device__ float g_q[(size_t)MTOT*DM];
__device__ float g_k[(size_t)MTOT*DM];
__device__ float g_v[(size_t)MTOT*DM];
__device__ float g_z[(size_t)MTOT*DM];

// ---------------------------------------------------------------------------
// QKV projection: C[m, which*1024 + h*64+e] = sum_d x[m,d]*W[which][h,d,e]
// Classic 128x128x8 SGEMM, 256 threads, 8x8 thread tile. Bias + 0.125 scale
// (for Q) folded into the epilogue.
// grid: (24, 32)  [nblk 0..23 -> which=nblk/8, mblk 0..31]
// ---------------------------------------------------------------------------
__global__ __launch_bounds__(256, 2)
void qkv_gemm(const float* __restrict__ x,
              const float* __restrict__ Wq, const float* __restrict__ Wk,
              const float* __restrict__ Wv,
              const float* __restrict__ bq, const float* __restrict__ bk,
              const float* __restrict__ bv)
{
    __shared__ float As[8][128];   // [k][m] transposed
    __shared__ float Bs[8][128];   // [k][n]

    const int tid  = threadIdx.x;
    const int nblk = blockIdx.x;
    const int mblk = blockIdx.y;
    const int which = nblk >> 3;
    const int nbase = (nblk & 7) << 7;           // 0..896 within [0,1024)

    const float* __restrict__ W    = (which==0) ? Wq : ((which==1) ? Wk : Wv);
    const float* __restrict__ bias = (which==0) ? bq : ((which==1) ? bk : bv);
    float* out = (which==0) ? g_q : ((which==1) ? g_k : g_v);

    const int m0g  = mblk << 7;
    const int tm   = tid >> 4;          // 0..15
    const int tn   = tid & 15;          // 0..15
    const int arow = tid >> 1;          // 0..127
    const int acol = (tid & 1) << 2;    // 0 or 4
    const int brow = tid >> 5;          // 0..7
    const int bcol = (tid & 31) << 2;   // 0..124

    // B column pointer: nn = nbase+bcol -> head h, elem e. float4 along e is
    // contiguous (e%4==0 so never crosses a head boundary).
    const int nn_b = nbase + bcol;
    const int h_b  = nn_b >> 6;
    const int e_b  = nn_b & 63;
    const float* __restrict__ Wcol = W + (size_t)h_b * DM * DH + e_b;

    float acc[8][8];
#pragma unroll
    for (int i = 0; i < 8; i++)
#pragma unroll
        for (int j = 0; j < 8; j++) acc[i][j] = 0.f;

    for (int k0 = 0; k0 < DM; k0 += 8) {
        float4 av  = *(const float4*)(x + (size_t)(m0g + arow) * DM + k0 + acol);
        float4 bv4 = *(const float4*)(Wcol + (size_t)(k0 + brow) * DH);
        __syncthreads();
        As[acol+0][arow] = av.x; As[acol+1][arow] = av.y;
        As[acol+2][arow] = av.z; As[acol+3][arow] = av.w;
        *(float4*)&Bs[brow][bcol] = bv4;
        __syncthreads();
#pragma unroll
        for (int kk = 0; kk < 8; kk++) {
            float4 a0 = *(const float4*)&As[kk][tm << 3];
            float4 a1 = *(const float4*)&As[kk][(tm << 3) + 4];
            float4 b0 = *(const float4*)&Bs[kk][tn << 3];
            float4 b1 = *(const float4*)&Bs[kk][(tn << 3) + 4];
            float a[8] = {a0.x,a0.y,a0.z,a0.w,a1.x,a1.y,a1.z,a1.w};
            float bb[8]= {b0.x,b0.y,b0.z,b0.w,b1.x,b1.y,b1.z,b1.w};
#pragma unroll
            for (int i = 0; i < 8; i++)
#pragma unroll
                for (int j = 0; j < 8; j++) acc[i][j] += a[i] * bb[j];
        }
    }

    const float scale = (which == 0) ? 0.125f : 1.0f;  // fold 1/sqrt(64) into Q
#pragma unroll
    for (int i = 0; i < 8; i++) {
        const int m = m0g + (tm << 3) + i;
#pragma unroll
        for (int j = 0; j < 8; j += 4) {
            const int nn = nbase + (tn << 3) + j;
            float4 r;
            r.x = (acc[i][j+0] + bias[nn+0]) * scale;
            r.y = (acc[i][j+1] + bias[nn+1]) * scale;
            r.z = (acc[i][j+2] + bias[nn+2]) * scale;
            r.w = (acc[i][j+3] + bias[nn+3]) * scale;
            *(float4*)(out + (size_t)m * DM + nn) = r;
        }
    }
}

// ---------------------------------------------------------------------------
// Output projection: out[m,d] = sum_r g_z[m,r] * W_O[r,d] + b_O[d]
// W_O [h,e,d] flattens exactly to row-major [1024,1024].
// grid: (8, 32)
// ---------------------------------------------------------------------------
__global__ __launch_bounds__(256, 2)
void proj_gemm(const float* __restrict__ B,
               const float* __restrict__ bias,
               float* __restrict__ C)
{
    __shared__ float As[8][128];
    __shared__ float Bs[8][128];

    const int tid  = threadIdx.x;
    const int nbase = blockIdx.x << 7;
    const int m0g   = blockIdx.y << 7;
    const int tm   = tid >> 4;
    const int tn   = tid & 15;
    const int arow = tid >> 1;
    const int acol = (tid & 1) << 2;
    const int brow = tid >> 5;
    const int bcol = (tid & 31) << 2;

    float acc[8][8];
#pragma unroll
    for (int i = 0; i < 8; i++)
#pragma unroll
        for (int j = 0; j < 8; j++) acc[i][j] = 0.f;

    for (int k0 = 0; k0 < DM; k0 += 8) {
        float4 av  = *(const float4*)(g_z + (size_t)(m0g + arow) * DM + k0 + acol);
        float4 bv4 = *(const float4*)(B + (size_t)(k0 + brow) * DM + nbase + bcol);
        __syncthreads();
        As[acol+0][arow] = av.x; As[acol+1][arow] = av.y;
        As[acol+2][arow] = av.z; As[acol+3][arow] = av.w;
        *(float4*)&Bs[brow][bcol] = bv4;
        __syncthreads();
#pragma unroll
        for (int kk = 0; kk < 8; kk++) {
            float4 a0 = *(const float4*)&As[kk][tm << 3];
            float4 a1 = *(const float4*)&As[kk][(tm << 3) + 4];
            float4 b0 = *(const float4*)&Bs[kk][tn << 3];
            float4 b1 = *(const float4*)&Bs[kk][(tn << 3) + 4];
            float a[8] = {a0.x,a0.y,a0.z,a0.w,a1.x,a1.y,a1.z,a1.w};
            float bb[8]= {b0.x,b0.y,b0.z,b0.w,b1.x,b1.y,b1.z,b1.w};
#pragma unroll
            for (int i = 0; i < 8; i++)
#pragma unroll
                for (int j = 0; j < 8; j++) acc[i][j] += a[i] * bb[j];
        }
    }

#pragma unroll
    for (int i = 0; i < 8; i++) {
        const int m = m0g + (tm << 3) + i;
#pragma unroll
        for (int j = 0; j < 8; j += 4) {
            const int n = nbase + (tn << 3) + j;
            float4 r;
            r.x = acc[i][j+0] + bias[n+0];
            r.y = acc[i][j+1] + bias[n+1];
            r.z = acc[i][j+2] + bias[n+2];
            r.w = acc[i][j+3] + bias[n+3];
            *(float4*)(C + (size_t)m * DM + n) = r;
        }
    }
}

// ---------------------------------------------------------------------------
// Flash attention (causal), fp32. BQ=BK=64, D=64, 256 threads (16x16),
// 4x4 register micro-tiles for both S=QK^T and O+=PV. Scale already folded
// into Q. Writes z[m, h*64+d] to g_z.
// grid: (SEQ/64=32, NH=16, NB=2); dyn smem = 3*64*LDP*4 = 52224 B
// ---------------------------------------------------------------------------
__global__ __launch_bounds__(256)
void attn_kernel()
{
    extern __shared__ float sm[];
    float* Qt  = sm;                 // [64 d][LDP] transposed Q: Qt[d][q]
    float* KPt = sm + 64 * LDP;      // Kt[d][k], reused as Pt[k][q]
    float* Vs  = sm + 2 * 64 * LDP;  // V[k][d]

    const int tid = threadIdx.x;
    const int tx  = tid & 15;
    const int ty  = tid >> 4;
    const int qi  = blockIdx.x;
    const int h   = blockIdx.y;
    const int b   = blockIdx.z;
    const size_t rowbase = (size_t)b * SEQ;
    const int col0 = h * DH;
    const int q0 = ty << 2;   // this thread's 4 q-rows (also O rows)
    const int x4 = tx << 2;   // this thread's 4 k-cols (S) / d-cols (O)

    // Load Q tile transposed (coalesced in d; padded store avoids 32-way conflicts)
#pragma unroll
    for (int it = 0; it < 16; ++it) {
        int idx = it * 256 + tid;
        int r = idx >> 6, d = idx & 63;
        Qt[d * LDP + r] = g_q[(rowbase + (size_t)qi * 64 + r) * DM + col0 + d];
    }

    float m_i[4], l_i[4], accO[4][4];
#pragma unroll
    for (int i = 0; i < 4; i++) {
        m_i[i] = -1e30f; l_i[i] = 0.f;
#pragma unroll
        for (int j = 0; j < 4; j++) accO[i][j] = 0.f;
    }
    __syncthreads();

    for (int kb = 0; kb <= qi; ++kb) {
        // Load K (transposed) and V tiles
#pragma unroll
        for (int it = 0; it < 16; ++it) {
            int idx = it * 256 + tid;
            int r = idx >> 6, d = idx & 63;
            size_t g = (rowbase + (size_t)kb * 64 + r) * DM + col0 + d;
            KPt[d * LDP + r] = g_k[g];
            Vs[r * LDP + d]  = g_v[g];
        }
        __syncthreads();

        // S = Q K^T (64x64x64), 4x4 per thread
        float s[4][4];
#pragma unroll
        for (int i = 0; i < 4; i++)
#pragma unroll
            for (int j = 0; j < 4; j++) s[i][j] = 0.f;

#pragma unroll 8
        for (int kk = 0; kk < 64; kk++) {
            float4 a = *(const float4*)&Qt[kk * LDP + q0];
            float4 c = *(const float4*)&KPt[kk * LDP + x4];
            float aa[4] = {a.x, a.y, a.z, a.w};
            float cc[4] = {c.x, c.y, c.z, c.w};
#pragma unroll
            for (int i = 0; i < 4; i++)
#pragma unroll
                for (int j = 0; j < 4; j++) s[i][j] += aa[i] * cc[j];
        }

        if (kb == qi) {  // causal mask on diagonal block
            const int gq0 = qi * 64 + q0, gk0 = kb * 64 + x4;
#pragma unroll
            for (int i = 0; i < 4; i++)
#pragma unroll
                for (int j = 0; j < 4; j++)
                    if (gk0 + j > gq0 + i) s[i][j] = -1e30f;
        }

        // Online softmax (row groups = 16 lanes sharing ty)
#pragma unroll
        for (int i = 0; i < 4; i++) {
            float rm = fmaxf(fmaxf(s[i][0], s[i][1]), fmaxf(s[i][2], s[i][3]));
#pragma unroll
            for (int o = 8; o >= 1; o >>= 1)
                rm = fmaxf(rm, __shfl_xor_sync(0xffffffffu, rm, o));
            float mnew = fmaxf(m_i[i], rm);
            float corr = __expf(m_i[i] - mnew);   // 0 on first block (m=-1e30)
            m_i[i] = mnew;
            float rs = 0.f;
#pragma unroll
            for (int j = 0; j < 4; j++) {
                float p = __expf(s[i][j] - mnew);
                s[i][j] = p; rs += p;
            }
#pragma unroll
            for (int o = 8; o >= 1; o >>= 1)
                rs += __shfl_xor_sync(0xffffffffu, rs, o);
            l_i[i] = l_i[i] * corr + rs;
#pragma unroll
            for (int j = 0; j < 4; j++) accO[i][j] *= corr;
        }

        __syncthreads();   // all S reads of KPt done before overwriting with P^T
#pragma unroll
        for (int j = 0; j < 4; j++) {
            float4 pv = make_float4(s[0][j], s[1][j], s[2][j], s[3][j]);
            *(float4*)&KPt[(x4 + j) * LDP + q0] = pv;   // Pt[k][q]
        }
        __syncthreads();

        // O += P V (64x64x64), 4x4 per thread
#pragma unroll 8
        for (int kc = 0; kc < 64; kc++) {
            float4 a = *(const float4*)&KPt[kc * LDP + q0];
            float4 v = *(const float4*)&Vs[kc * LDP + x4];
            float aa[4] = {a.x, a.y, a.z, a.w};
            float vv[4] = {v.x, v.y, v.z, v.w};
#pragma unroll
            for (int i = 0; i < 4; i++)
#pragma unroll
                for (int j = 0; j < 4; j++) accO[i][j] += aa[i] * vv[j];
        }
        __syncthreads();   // protect KPt/Vs before next iteration's loads
    }

    // z = O / l
#pragma unroll
    for (int i = 0; i < 4; i++) {
        float inv = 1.f / l_i[i];
        size_t row = (rowbase + (size_t)qi * 64 + q0 + i) * DM + col0 + x4;
        *(float4*)(g_z + row) = make_float4(accO[i][0] * inv, accO[i][1] * inv,
                                            accO[i][2] * inv, accO[i][3] * inv);
    }
}

// ---------------------------------------------------------------------------
extern "C" void kernel_launch(void* const* d_in, const int* in_sizes, int n_in,
                              void* d_out, int out_size)
{
    const float* x  = (const float*)d_in[0];
    const float* Wq = (const float*)d_in[1];
    const float* Wk = (const float*)d_in[2];
    const float* Wv = (const float*)d_in[3];
    const float* Wo = (const float*)d_in[4];
    const float* bq = (const float*)d_in[5];
    const float* bk = (const float*)d_in[6];
    const float* bv = (const float*)d_in[7];
    const float* bo = (const float*)d_in[8];
    float* out = (float*)d_out;

    const int attn_smem = 3 * 64 * LDP * (int)sizeof(float);  // 52224 B
    cudaFuncSetAttribute(attn_kernel,
                         cudaFuncAttributeMaxDynamicSharedMemorySize, attn_smem);

    dim3 g1(24, 32);
    qkv_gemm<<<g1, 256>>>(x, Wq, Wk, Wv, bq, bk, bv);

    dim3 g2(SEQ / 64, NH, NB);
    attn_kernel<<<g2, 256, attn_smem>>>();

    dim3 g3(8, 32);
    proj_gemm<<<g3, 256>>>(Wo, bo, out);
}

// round 4
// speedup vs baseline: 1.4723x; 1.4723x over previous
#include <cuda_runtime.h>
#include <cuda_bf16.h>
#include <cstdint>
#include <math.h>

#define DM   1024
#define DH   64
#define NH   16
#define SEQ  2048
#define NB   2
#define MTOT (NB*SEQ)   // 4096
#define LDP  68

// ---------------- scratch (__device__ globals; no allocs allowed) ----------
__device__ float g_q[(size_t)MTOT*DM];
__device__ float g_k[(size_t)MTOT*DM];
__device__ float g_v[(size_t)MTOT*DM];
__device__ float g_z[(size_t)MTOT*DM];

__device__ __align__(16) __nv_bfloat16 s_xh[(size_t)MTOT*DM];  // x hi/lo [M,K]
__device__ __align__(16) __nv_bfloat16 s_xl[(size_t)MTOT*DM];
__device__ __align__(16) __nv_bfloat16 s_zh[(size_t)MTOT*DM];  // z hi/lo [M,K]
__device__ __align__(16) __nv_bfloat16 s_zl[(size_t)MTOT*DM];
__device__ __align__(16) __nv_bfloat16 s_wh[(size_t)3*DM*DM];  // Wqkv^T [3072,1024]
__device__ __align__(16) __nv_bfloat16 s_wl[(size_t)3*DM*DM];
__device__ __align__(16) __nv_bfloat16 s_oh[(size_t)DM*DM];    // Wo^T [1024,1024]
__device__ __align__(16) __nv_bfloat16 s_ol[(size_t)DM*DM];

// ---------------- PTX helpers (sm_103 base ISA only: HMMA/LDSM/LDGSTS) -----
__device__ __forceinline__ uint32_t smem_u32(const void* p) {
    uint32_t a;
    asm("{ .reg .u64 t; cvta.to.shared.u64 t, %1; cvt.u32.u64 %0, t; }"
        : "=r"(a) : "l"(p));
    return a;
}

__device__ __forceinline__ void cp_async16(uint32_t dst, const void* src) {
    asm volatile("cp.async.cg.shared.global [%0], [%1], 16;"
                 :: "r"(dst), "l"(src) : "memory");
}
#define CP_COMMIT()  asm volatile("cp.async.commit_group;" ::: "memory")
#define CP_WAIT0()   asm volatile("cp.async.wait_group 0;" ::: "memory")

__device__ __forceinline__ void ldsm4(uint32_t& r0, uint32_t& r1,
                                      uint32_t& r2, uint32_t& r3, uint32_t addr) {
    asm volatile("ldmatrix.sync.aligned.m8n8.x4.shared.b16 {%0,%1,%2,%3}, [%4];"
                 : "=r"(r0), "=r"(r1), "=r"(r2), "=r"(r3) : "r"(addr));
}

__device__ __forceinline__ void mma16816(float* d, const uint32_t* a,
                                         uint32_t b0, uint32_t b1) {
    asm volatile(
        "mma.sync.aligned.m16n8k16.row.col.f32.bf16.bf16.f32 "
        "{%0,%1,%2,%3}, {%4,%5,%6,%7}, {%8,%9}, {%0,%1,%2,%3};"
        : "+f"(d[0]), "+f"(d[1]), "+f"(d[2]), "+f"(d[3])
        : "r"(a[0]), "r"(a[1]), "r"(a[2]), "r"(a[3]), "r"(b0), "r"(b1));
}

// ---------------- conversion kernels ---------------------------------------
__global__ void split_plain(const float* __restrict__ in, int use_gz)
{
    const float* src = use_gz ? g_z : in;
    __nv_bfloat16* oh = use_gz ? s_zh : s_xh;
    __nv_bfloat16* ol = use_gz ? s_zl : s_xl;
    size_t i4 = (size_t)blockIdx.x * blockDim.x + threadIdx.x;
    float4 v = ((const float4*)src)[i4];
    __nv_bfloat162 h0, h1, l0, l1;
    h0.x = __float2bfloat16(v.x); l0.x = __float2bfloat16(v.x - __bfloat162float(h0.x));
    h0.y = __float2bfloat16(v.y); l0.y = __float2bfloat16(v.y - __bfloat162float(h0.y));
    h1.x = __float2bfloat16(v.z); l1.x = __float2bfloat16(v.z - __bfloat162float(h1.x));
    h1.y = __float2bfloat16(v.w); l1.y = __float2bfloat16(v.w - __bfloat162float(h1.y));
    ((__nv_bfloat162*)oh)[i4*2]   = h0;
    ((__nv_bfloat162*)oh)[i4*2+1] = h1;
    ((__nv_bfloat162*)ol)[i4*2]   = l0;
    ((__nv_bfloat162*)ol)[i4*2+1] = l1;
}

// transpose [R,C] fp32 (block z: offset z*R*C both sides) -> [C,R] bf16 hi/lo
__global__ void transpose_split(const float* __restrict__ in, int out_sel, int R, int C)
{
    __shared__ float t[64][65];
    size_t zoff = (size_t)blockIdx.z * R * C;
    const float* src = in + zoff;
    __nv_bfloat16* oh = (out_sel < 3) ? (s_wh + (size_t)out_sel*DM*DM) : s_oh;
    __nv_bfloat16* ol = (out_sel < 3) ? (s_wl + (size_t)out_sel*DM*DM) : s_ol;
    oh += zoff;
    ol += zoff;
    int r0 = blockIdx.x * 64, c0 = blockIdx.y * 64;
    for (int i = threadIdx.x; i < 64*64; i += 256) {
        int r = i >> 6, c = i & 63;
        t[r][c] = src[(size_t)(r0 + r) * C + c0 + c];
    }
    __syncthreads();
    for (int i = threadIdx.x; i < 64*64; i += 256) {
        int c = i >> 6, r = i & 63;
        float v = t[r][c];
        __nv_bfloat16 h = __float2bfloat16(v);
        size_t o = (size_t)(c0 + c) * R + r0 + r;
        oh[o] = h;
        ol[o] = __float2bfloat16(v - __bfloat162float(h));
    }
}

// ---------------- HMMA GEMM (bf16x3 split, mma.sync m16n8k16) --------------
// CTA tile 128(M)x128(N), K-chunk 32. 8 warps: wm=wid&3 (32 rows), wn=wid>>2
// (64 cols). Per warp: 2 m16-tiles x 8 n8-tiles, fp32 accum, 3 passes
// (Ah*Bh + Ah*Bl + Al*Bh). Smem stride 80B -> conflict-free ldmatrix.
#define ASZ   10240                 // 128 rows * 80B
#define BUFSZ (4*ASZ)               // Ah Al Bh Bl
#define SMEM_HM (2*BUFSZ)           // 81920 (double buffered)

__global__ __launch_bounds__(256, 2)
void hmma_gemm(int qkv_mode, float* __restrict__ o0,
               const float* __restrict__ b0, const float* __restrict__ b1,
               const float* __restrict__ b2)
{
    extern __shared__ char smbuf[];
    const uint32_t sb = smem_u32(smbuf);
    const int tid  = threadIdx.x;
    const int wid  = tid >> 5;
    const int lane = tid & 31;

    const __nv_bfloat16 *Ah, *Al, *Bh, *Bl;
    if (qkv_mode) { Ah = s_xh; Al = s_xl; Bh = s_wh; Bl = s_wl; }
    else          { Ah = s_zh; Al = s_zl; Bh = s_oh; Bl = s_ol; }

    const int n0g = blockIdx.x << 7;   // global N base (row in B)
    const int m0g = blockIdx.y << 7;   // global M base

    const int wm  = wid & 3;
    const int wn  = wid >> 2;
    const int m0w = wm << 5;           // warp row base within tile
    const int n0w = wn << 6;           // warp col base within tile

    // ldmatrix per-lane address offset (mid = lane>>3):
    //   row += (mid&1)*8 ; byte col += (mid>>1)*16
    const uint32_t ldsm_off =
        (uint32_t)((((lane >> 3) & 1) * 8 + (lane & 7)) * 80 + (lane >> 4) * 16);

    // staging map: 8 cp.asyncs/thread; part 0..3 = Ah,Al,Bh,Bl
    int s_part[8], s_r[8], s_c[8];
#pragma unroll
    for (int i = 0; i < 8; ++i) {
        int idx = i * 256 + tid;
        s_part[i] = idx >> 9;
        int u = idx & 511;
        s_r[i] = u >> 2;
        s_c[i] = u & 3;
    }

    float acc[2][8][4];
#pragma unroll
    for (int mi = 0; mi < 2; ++mi)
#pragma unroll
        for (int ni = 0; ni < 8; ++ni)
#pragma unroll
            for (int c = 0; c < 4; ++c) acc[mi][ni][c] = 0.f;

    // ---- stage chunk 0 ----
    {
        const uint32_t bw = sb;
#pragma unroll
        for (int i = 0; i < 8; ++i) {
            const int part = s_part[i], r = s_r[i], cc = s_c[i];
            const __nv_bfloat16* srcb =
                (part == 0) ? (Ah + (size_t)(m0g + r) * DM) :
                (part == 1) ? (Al + (size_t)(m0g + r) * DM) :
                (part == 2) ? (Bh + (size_t)(n0g + r) * DM) :
                              (Bl + (size_t)(n0g + r) * DM);
            cp_async16(bw + (uint32_t)(part * ASZ + r * 80 + cc * 16),
                       srcb + cc * 8);
        }
        CP_COMMIT();
        CP_WAIT0();
        __syncthreads();
    }

    for (int c = 0; c < 32; ++c) {
        const uint32_t bufr = sb + (uint32_t)((c & 1) * BUFSZ);

        if (c < 31) {
            const int k0 = (c + 1) << 5;
            const uint32_t bw = sb + (uint32_t)(((c + 1) & 1) * BUFSZ);
#pragma unroll
            for (int i = 0; i < 8; ++i) {
                const int part = s_part[i], r = s_r[i], cc = s_c[i];
                const __nv_bfloat16* srcb =
                    (part == 0) ? (Ah + (size_t)(m0g + r) * DM) :
                    (part == 1) ? (Al + (size_t)(m0g + r) * DM) :
                    (part == 2) ? (Bh + (size_t)(n0g + r) * DM) :
                                  (Bl + (size_t)(n0g + r) * DM);
                cp_async16(bw + (uint32_t)(part * ASZ + r * 80 + cc * 16),
                           srcb + k0 + cc * 8);
            }
            CP_COMMIT();
        }

        // ---- compute on bufr ----
#pragma unroll
        for (int kh = 0; kh < 2; ++kh) {
            const uint32_t kb = (uint32_t)(kh * 32);   // 16 elems * 2B
#pragma unroll
            for (int pass = 0; pass < 3; ++pass) {
                const uint32_t Abase = bufr + ((pass == 2) ? (uint32_t)ASZ : 0u);
                const uint32_t Bbase = bufr + (uint32_t)(2 * ASZ)
                                            + ((pass == 1) ? (uint32_t)ASZ : 0u);
                uint32_t a[2][4];
#pragma unroll
                for (int mi = 0; mi < 2; ++mi)
                    ldsm4(a[mi][0], a[mi][1], a[mi][2], a[mi][3],
                          Abase + (uint32_t)((m0w + mi * 16) * 80) + kb + ldsm_off);
                uint32_t b[4][4];
#pragma unroll
                for (int nj = 0; nj < 4; ++nj)
                    ldsm4(b[nj][0], b[nj][1], b[nj][2], b[nj][3],
                          Bbase + (uint32_t)((n0w + nj * 16) * 80) + kb + ldsm_off);
#pragma unroll
                for (int mi = 0; mi < 2; ++mi)
#pragma unroll
                    for (int ni = 0; ni < 8; ++ni) {
                        const int nj = ni >> 1, hi = ni & 1;
                        mma16816(acc[mi][ni], a[mi], b[nj][hi], b[nj][hi + 2]);
                    }
            }
        }

        if (c < 31) {
            CP_WAIT0();
            __syncthreads();
        }
    }

    // ---- epilogue ----
    const float* bias;
    float* outp;
    float scale;
    int ncl;
    if (qkv_mode) {
        const int which = n0g >> 10;
        ncl   = n0g & 1023;
        bias  = (which == 0) ? b0 : ((which == 1) ? b1 : b2);
        outp  = (which == 0) ? g_q : ((which == 1) ? g_k : g_v);
        scale = (which == 0) ? 0.125f : 1.0f;
    } else {
        bias = b0; outp = o0; scale = 1.0f; ncl = n0g;
    }

#pragma unroll
    for (int mi = 0; mi < 2; ++mi) {
        const int r0 = m0g + m0w + mi * 16 + (lane >> 2);
#pragma unroll
        for (int ni = 0; ni < 8; ++ni) {
            const int col = ncl + n0w + ni * 8 + ((lane & 3) << 1);
            const float bx = bias[col], by = bias[col + 1];
            float2 w0, w1;
            w0.x = (acc[mi][ni][0] + bx) * scale;
            w0.y = (acc[mi][ni][1] + by) * scale;
            w1.x = (acc[mi][ni][2] + bx) * scale;
            w1.y = (acc[mi][ni][3] + by) * scale;
            *(float2*)(outp + (size_t)r0 * DM + col)       = w0;
            *(float2*)(outp + (size_t)(r0 + 8) * DM + col) = w1;
        }
    }
}

// ---------------- flash attention (fp32, unchanged — passed round 1) -------
__global__ __launch_bounds__(256)
void attn_kernel()
{
    extern __shared__ float smf[];
    float* Qt  = smf;
    float* KPt = smf + 64 * LDP;
    float* Vs  = smf + 2 * 64 * LDP;

    const int tid = threadIdx.x;
    const int tx  = tid & 15;
    const int ty  = tid >> 4;
    const int qi  = blockIdx.x;
    const int h   = blockIdx.y;
    const int b   = blockIdx.z;
    const size_t rowbase = (size_t)b * SEQ;
    const int col0 = h * DH;
    const int q0 = ty << 2;
    const int x4 = tx << 2;

#pragma unroll
    for (int it = 0; it < 16; ++it) {
        int idx = it * 256 + tid;
        int r = idx >> 6, d = idx & 63;
        Qt[d * LDP + r] = g_q[(rowbase + (size_t)qi * 64 + r) * DM + col0 + d];
    }

    float m_i[4], l_i[4], accO[4][4];
#pragma unroll
    for (int i = 0; i < 4; i++) {
        m_i[i] = -1e30f;
        l_i[i] = 0.f;
#pragma unroll
        for (int j = 0; j < 4; j++) accO[i][j] = 0.f;
    }
    __syncthreads();

    for (int kb = 0; kb <= qi; ++kb) {
#pragma unroll
        for (int it = 0; it < 16; ++it) {
            int idx = it * 256 + tid;
            int r = idx >> 6, d = idx & 63;
            size_t g = (rowbase + (size_t)kb * 64 + r) * DM + col0 + d;
            KPt[d * LDP + r] = g_k[g];
            Vs[r * LDP + d]  = g_v[g];
        }
        __syncthreads();

        float s[4][4];
#pragma unroll
        for (int i = 0; i < 4; i++)
#pragma unroll
            for (int j = 0; j < 4; j++) s[i][j] = 0.f;

#pragma unroll 8
        for (int kk = 0; kk < 64; kk++) {
            float4 a = *(const float4*)&Qt[kk * LDP + q0];
            float4 c = *(const float4*)&KPt[kk * LDP + x4];
            float aa[4] = {a.x, a.y, a.z, a.w};
            float cc[4] = {c.x, c.y, c.z, c.w};
#pragma unroll
            for (int i = 0; i < 4; i++)
#pragma unroll
                for (int j = 0; j < 4; j++) s[i][j] += aa[i] * cc[j];
        }

        if (kb == qi) {
            const int gq0 = qi * 64 + q0, gk0 = kb * 64 + x4;
#pragma unroll
            for (int i = 0; i < 4; i++)
#pragma unroll
                for (int j = 0; j < 4; j++)
                    if (gk0 + j > gq0 + i) s[i][j] = -1e30f;
        }

#pragma unroll
        for (int i = 0; i < 4; i++) {
            float rm = fmaxf(fmaxf(s[i][0], s[i][1]), fmaxf(s[i][2], s[i][3]));
#pragma unroll
            for (int o = 8; o >= 1; o >>= 1)
                rm = fmaxf(rm, __shfl_xor_sync(0xffffffffu, rm, o));
            float mnew = fmaxf(m_i[i], rm);
            float corr = __expf(m_i[i] - mnew);
            m_i[i] = mnew;
            float rs = 0.f;
#pragma unroll
            for (int j = 0; j < 4; j++) {
                float p = __expf(s[i][j] - mnew);
                s[i][j] = p;
                rs += p;
            }
#pragma unroll
            for (int o = 8; o >= 1; o >>= 1)
                rs += __shfl_xor_sync(0xffffffffu, rs, o);
            l_i[i] = l_i[i] * corr + rs;
#pragma unroll
            for (int j = 0; j < 4; j++) accO[i][j] *= corr;
        }

        __syncthreads();
#pragma unroll
        for (int j = 0; j < 4; j++) {
            float4 pv = make_float4(s[0][j], s[1][j], s[2][j], s[3][j]);
            *(float4*)&KPt[(x4 + j) * LDP + q0] = pv;
        }
        __syncthreads();

#pragma unroll 8
        for (int kc = 0; kc < 64; kc++) {
            float4 a = *(const float4*)&KPt[kc * LDP + q0];
            float4 v = *(const float4*)&Vs[kc * LDP + x4];
            float aa[4] = {a.x, a.y, a.z, a.w};
            float vv[4] = {v.x, v.y, v.z, v.w};
#pragma unroll
            for (int i = 0; i < 4; i++)
#pragma unroll
                for (int j = 0; j < 4; j++) accO[i][j] += aa[i] * vv[j];
        }
        __syncthreads();
    }

#pragma unroll
    for (int i = 0; i < 4; i++) {
        float inv = 1.f / l_i[i];
        size_t row = (rowbase + (size_t)qi * 64 + q0 + i) * DM + col0 + x4;
        *(float4*)(g_z + row) = make_float4(accO[i][0] * inv, accO[i][1] * inv,
                                            accO[i][2] * inv, accO[i][3] * inv);
    }
}

// ---------------------------------------------------------------------------
extern "C" void kernel_launch(void* const* d_in, const int* in_sizes, int n_in,
                              void* d_out, int out_size)
{
    const float* x  = (const float*)d_in[0];
    const float* Wq = (const float*)d_in[1];
    const float* Wk = (const float*)d_in[2];
    const float* Wv = (const float*)d_in[3];
    const float* Wo = (const float*)d_in[4];
    const float* bq = (const float*)d_in[5];
    const float* bk = (const float*)d_in[6];
    const float* bv = (const float*)d_in[7];
    const float* bo = (const float*)d_in[8];
    float* out = (float*)d_out;

    const int attn_smem = 3 * 64 * LDP * (int)sizeof(float);
    cudaFuncSetAttribute(attn_kernel,
                         cudaFuncAttributeMaxDynamicSharedMemorySize, attn_smem);
    cudaFuncSetAttribute(hmma_gemm,
                         cudaFuncAttributeMaxDynamicSharedMemorySize, SMEM_HM);

    split_plain<<<(MTOT*DM)/(256*4), 256>>>(x, 0);
    transpose_split<<<dim3(16, 1, 16), 256>>>(Wq, 0, DM, DH);
    transpose_split<<<dim3(16, 1, 16), 256>>>(Wk, 1, DM, DH);
    transpose_split<<<dim3(16, 1, 16), 256>>>(Wv, 2, DM, DH);
    transpose_split<<<dim3(16, 16, 1), 256>>>(Wo, 3, DM, DM);

    hmma_gemm<<<dim3(24, 32), 256, SMEM_HM>>>(1, nullptr, bq, bk, bv);

    attn_kernel<<<dim3(SEQ / 64, NH, NB), 256, attn_smem>>>();

    split_plain<<<(MTOT*DM)/(256*4), 256>>>(nullptr, 1);
    hmma_gemm<<<dim3(8, 32), 256, SMEM_HM>>>(0, out, bo, nullptr, nullptr);
}

// round 5
// speedup vs baseline: 2.3595x; 1.6026x over previous
#include <cuda_runtime.h>
#include <cuda_bf16.h>
#include <cstdint>
#include <math.h>

#define DM   1024
#define DH   64
#define NH   16
#define SEQ  2048
#define NB   2
#define MTOT (NB*SEQ)   // 4096

// ---------------- scratch (__device__ globals; no allocs allowed) ----------
__device__ __align__(16) __nv_bfloat16 s_xh[(size_t)MTOT*DM];  // x hi/lo [M,K]
__device__ __align__(16) __nv_bfloat16 s_xl[(size_t)MTOT*DM];
__device__ __align__(16) __nv_bfloat16 s_zh[(size_t)MTOT*DM];  // z hi/lo [M,K]
__device__ __align__(16) __nv_bfloat16 s_zl[(size_t)MTOT*DM];
__device__ __align__(16) __nv_bfloat16 s_wh[(size_t)3*DM*DM];  // Wqkv^T [3072,1024]
__device__ __align__(16) __nv_bfloat16 s_wl[(size_t)3*DM*DM];
__device__ __align__(16) __nv_bfloat16 s_oh[(size_t)DM*DM];    // Wo^T [1024,1024]
__device__ __align__(16) __nv_bfloat16 s_ol[(size_t)DM*DM];
// attention operands, bf16 hi/lo, layout [m, h*64+e]
__device__ __align__(16) __nv_bfloat16 a_qh[(size_t)MTOT*DM];
__device__ __align__(16) __nv_bfloat16 a_ql[(size_t)MTOT*DM];
__device__ __align__(16) __nv_bfloat16 a_kh[(size_t)MTOT*DM];
__device__ __align__(16) __nv_bfloat16 a_kl[(size_t)MTOT*DM];
__device__ __align__(16) __nv_bfloat16 a_vh[(size_t)MTOT*DM];
__device__ __align__(16) __nv_bfloat16 a_vl[(size_t)MTOT*DM];

// ---------------- PTX helpers ----------------------------------------------
__device__ __forceinline__ uint32_t smem_u32(const void* p) {
    uint32_t a;
    asm("{ .reg .u64 t; cvta.to.shared.u64 t, %1; cvt.u32.u64 %0, t; }"
        : "=r"(a) : "l"(p));
    return a;
}
__device__ __forceinline__ void cp_async16(uint32_t dst, const void* src) {
    asm volatile("cp.async.cg.shared.global [%0], [%1], 16;"
                 :: "r"(dst), "l"(src) : "memory");
}
#define CP_COMMIT()  asm volatile("cp.async.commit_group;" ::: "memory")
#define CP_WAIT0()   asm volatile("cp.async.wait_group 0;" ::: "memory")
#define CP_WAIT1()   asm volatile("cp.async.wait_group 1;" ::: "memory")

__device__ __forceinline__ void ldsm4(uint32_t& r0, uint32_t& r1,
                                      uint32_t& r2, uint32_t& r3, uint32_t addr) {
    asm volatile("ldmatrix.sync.aligned.m8n8.x4.shared.b16 {%0,%1,%2,%3}, [%4];"
                 : "=r"(r0), "=r"(r1), "=r"(r2), "=r"(r3) : "r"(addr));
}
__device__ __forceinline__ void ldsm4t(uint32_t& r0, uint32_t& r1,
                                       uint32_t& r2, uint32_t& r3, uint32_t addr) {
    asm volatile("ldmatrix.sync.aligned.m8n8.x4.trans.shared.b16 {%0,%1,%2,%3}, [%4];"
                 : "=r"(r0), "=r"(r1), "=r"(r2), "=r"(r3) : "r"(addr));
}
__device__ __forceinline__ void mma16816(float* d, const uint32_t* a,
                                         uint32_t b0, uint32_t b1) {
    asm volatile(
        "mma.sync.aligned.m16n8k16.row.col.f32.bf16.bf16.f32 "
        "{%0,%1,%2,%3}, {%4,%5,%6,%7}, {%8,%9}, {%0,%1,%2,%3};"
        : "+f"(d[0]), "+f"(d[1]), "+f"(d[2]), "+f"(d[3])
        : "r"(a[0]), "r"(a[1]), "r"(a[2]), "r"(a[3]), "r"(b0), "r"(b1));
}
// pack (lo, hi) floats -> bf16x2 (lo in lower 16 bits)
__device__ __forceinline__ uint32_t packbf(float lo, float hi) {
    uint32_t r;
    asm("cvt.rn.bf16x2.f32 %0, %1, %2;" : "=r"(r) : "f"(hi), "f"(lo));
    return r;
}
__device__ __forceinline__ uint32_t packresid(float x, float y, uint32_t hp) {
    __nv_bfloat162 h = *reinterpret_cast<__nv_bfloat162*>(&hp);
    return packbf(x - __bfloat162float(h.x), y - __bfloat162float(h.y));
}
__device__ __forceinline__ void split_store(__nv_bfloat16* ph, __nv_bfloat16* pl,
                                            size_t off, float x, float y) {
    __nv_bfloat162 hh, ll;
    hh.x = __float2bfloat16(x); ll.x = __float2bfloat16(x - __bfloat162float(hh.x));
    hh.y = __float2bfloat16(y); ll.y = __float2bfloat16(y - __bfloat162float(hh.y));
    *(__nv_bfloat162*)(ph + off) = hh;
    *(__nv_bfloat162*)(pl + off) = ll;
}

// ---------------- conversion kernels ---------------------------------------
__global__ void split_plain(const float* __restrict__ in)
{
    size_t i4 = (size_t)blockIdx.x * blockDim.x + threadIdx.x;
    float4 v = ((const float4*)in)[i4];
    __nv_bfloat162 h0, h1, l0, l1;
    h0.x = __float2bfloat16(v.x); l0.x = __float2bfloat16(v.x - __bfloat162float(h0.x));
    h0.y = __float2bfloat16(v.y); l0.y = __float2bfloat16(v.y - __bfloat162float(h0.y));
    h1.x = __float2bfloat16(v.z); l1.x = __float2bfloat16(v.z - __bfloat162float(h1.x));
    h1.y = __float2bfloat16(v.w); l1.y = __float2bfloat16(v.w - __bfloat162float(h1.y));
    ((__nv_bfloat162*)s_xh)[i4*2]   = h0;
    ((__nv_bfloat162*)s_xh)[i4*2+1] = h1;
    ((__nv_bfloat162*)s_xl)[i4*2]   = l0;
    ((__nv_bfloat162*)s_xl)[i4*2+1] = l1;
}

__global__ void transpose_split(const float* __restrict__ in, int out_sel, int R, int C)
{
    __shared__ float t[64][65];
    size_t zoff = (size_t)blockIdx.z * R * C;
    const float* src = in + zoff;
    __nv_bfloat16* oh = (out_sel < 3) ? (s_wh + (size_t)out_sel*DM*DM) : s_oh;
    __nv_bfloat16* ol = (out_sel < 3) ? (s_wl + (size_t)out_sel*DM*DM) : s_ol;
    oh += zoff;
    ol += zoff;
    int r0 = blockIdx.x * 64, c0 = blockIdx.y * 64;
    for (int i = threadIdx.x; i < 64*64; i += 256) {
        int r = i >> 6, c = i & 63;
        t[r][c] = src[(size_t)(r0 + r) * C + c0 + c];
    }
    __syncthreads();
    for (int i = threadIdx.x; i < 64*64; i += 256) {
        int c = i >> 6, r = i & 63;
        float v = t[r][c];
        __nv_bfloat16 h = __float2bfloat16(v);
        size_t o = (size_t)(c0 + c) * R + r0 + r;
        oh[o] = h;
        ol[o] = __float2bfloat16(v - __bfloat162float(h));
    }
}

// ---------------- HMMA GEMM (bf16x3 split) — internals proven round 4 ------
#define ASZ   10240
#define BUFSZ (4*ASZ)
#define SMEM_HM (2*BUFSZ)

__global__ __launch_bounds__(256, 2)
void hmma_gemm(int qkv_mode, float* __restrict__ o0,
               const float* __restrict__ b0, const float* __restrict__ b1,
               const float* __restrict__ b2)
{
    extern __shared__ char smbuf[];
    const uint32_t sb = smem_u32(smbuf);
    const int tid  = threadIdx.x;
    const int wid  = tid >> 5;
    const int lane = tid & 31;

    const __nv_bfloat16 *Ah, *Al, *Bh, *Bl;
    if (qkv_mode) { Ah = s_xh; Al = s_xl; Bh = s_wh; Bl = s_wl; }
    else          { Ah = s_zh; Al = s_zl; Bh = s_oh; Bl = s_ol; }

    const int n0g = blockIdx.x << 7;
    const int m0g = blockIdx.y << 7;
    const int wm  = wid & 3;
    const int wn  = wid >> 2;
    const int m0w = wm << 5;
    const int n0w = wn << 6;

    const uint32_t ldsm_off =
        (uint32_t)((((lane >> 3) & 1) * 8 + (lane & 7)) * 80 + (lane >> 4) * 16);

    int s_part[8], s_r[8], s_c[8];
#pragma unroll
    for (int i = 0; i < 8; ++i) {
        int idx = i * 256 + tid;
        s_part[i] = idx >> 9;
        int u = idx & 511;
        s_r[i] = u >> 2;
        s_c[i] = u & 3;
    }

    float acc[2][8][4];
#pragma unroll
    for (int mi = 0; mi < 2; ++mi)
#pragma unroll
        for (int ni = 0; ni < 8; ++ni)
#pragma unroll
            for (int c = 0; c < 4; ++c) acc[mi][ni][c] = 0.f;

    {
        const uint32_t bw = sb;
#pragma unroll
        for (int i = 0; i < 8; ++i) {
            const int part = s_part[i], r = s_r[i], cc = s_c[i];
            const __nv_bfloat16* srcb =
                (part == 0) ? (Ah + (size_t)(m0g + r) * DM) :
                (part == 1) ? (Al + (size_t)(m0g + r) * DM) :
                (part == 2) ? (Bh + (size_t)(n0g + r) * DM) :
                              (Bl + (size_t)(n0g + r) * DM);
            cp_async16(bw + (uint32_t)(part * ASZ + r * 80 + cc * 16),
                       srcb + cc * 8);
        }
        CP_COMMIT();
        CP_WAIT0();
        __syncthreads();
    }

    for (int c = 0; c < 32; ++c) {
        const uint32_t bufr = sb + (uint32_t)((c & 1) * BUFSZ);

        if (c < 31) {
            const int k0 = (c + 1) << 5;
            const uint32_t bw = sb + (uint32_t)(((c + 1) & 1) * BUFSZ);
#pragma unroll
            for (int i = 0; i < 8; ++i) {
                const int part = s_part[i], r = s_r[i], cc = s_c[i];
                const __nv_bfloat16* srcb =
                    (part == 0) ? (Ah + (size_t)(m0g + r) * DM) :
                    (part == 1) ? (Al + (size_t)(m0g + r) * DM) :
                    (part == 2) ? (Bh + (size_t)(n0g + r) * DM) :
                                  (Bl + (size_t)(n0g + r) * DM);
                cp_async16(bw + (uint32_t)(part * ASZ + r * 80 + cc * 16),
                           srcb + k0 + cc * 8);
            }
            CP_COMMIT();
        }

#pragma unroll
        for (int kh = 0; kh < 2; ++kh) {
            const uint32_t kb = (uint32_t)(kh * 32);
#pragma unroll
            for (int pass = 0; pass < 3; ++pass) {
                const uint32_t Abase = bufr + ((pass == 2) ? (uint32_t)ASZ : 0u);
                const uint32_t Bbase = bufr + (uint32_t)(2 * ASZ)
                                            + ((pass == 1) ? (uint32_t)ASZ : 0u);
                uint32_t a[2][4];
#pragma unroll
                for (int mi = 0; mi < 2; ++mi)
                    ldsm4(a[mi][0], a[mi][1], a[mi][2], a[mi][3],
                          Abase + (uint32_t)((m0w + mi * 16) * 80) + kb + ldsm_off);
                uint32_t b[4][4];
#pragma unroll
                for (int nj = 0; nj < 4; ++nj)
                    ldsm4(b[nj][0], b[nj][1], b[nj][2], b[nj][3],
                          Bbase + (uint32_t)((n0w + nj * 16) * 80) + kb + ldsm_off);
#pragma unroll
                for (int mi = 0; mi < 2; ++mi)
#pragma unroll
                    for (int ni = 0; ni < 8; ++ni) {
                        const int nj = ni >> 1, hi = ni & 1;
                        mma16816(acc[mi][ni], a[mi], b[nj][hi], b[nj][hi + 2]);
                    }
            }
        }

        if (c < 31) {
            CP_WAIT0();
            __syncthreads();
        }
    }

    // ---- epilogue ----
    if (qkv_mode) {
        const int which = n0g >> 10;
        const int ncl   = n0g & 1023;
        const float* bias = (which == 0) ? b0 : ((which == 1) ? b1 : b2);
        __nv_bfloat16* oph = (which == 0) ? a_qh : ((which == 1) ? a_kh : a_vh);
        __nv_bfloat16* opl = (which == 0) ? a_ql : ((which == 1) ? a_kl : a_vl);
        const float scale = (which == 0) ? 0.125f : 1.0f;
#pragma unroll
        for (int mi = 0; mi < 2; ++mi) {
            const int r0 = m0g + m0w + mi * 16 + (lane >> 2);
#pragma unroll
            for (int ni = 0; ni < 8; ++ni) {
                const int col = ncl + n0w + ni * 8 + ((lane & 3) << 1);
                const float bx = bias[col], by = bias[col + 1];
                split_store(oph, opl, (size_t)r0 * DM + col,
                            (acc[mi][ni][0] + bx) * scale,
                            (acc[mi][ni][1] + by) * scale);
                split_store(oph, opl, (size_t)(r0 + 8) * DM + col,
                            (acc[mi][ni][2] + bx) * scale,
                            (acc[mi][ni][3] + by) * scale);
            }
        }
    } else {
#pragma unroll
        for (int mi = 0; mi < 2; ++mi) {
            const int r0 = m0g + m0w + mi * 16 + (lane >> 2);
#pragma unroll
            for (int ni = 0; ni < 8; ++ni) {
                const int col = n0g + n0w + ni * 8 + ((lane & 3) << 1);
                const float bx = b0[col], by = b0[col + 1];
                float2 w0, w1;
                w0.x = acc[mi][ni][0] + bx;  w0.y = acc[mi][ni][1] + by;
                w1.x = acc[mi][ni][2] + bx;  w1.y = acc[mi][ni][3] + by;
                *(float2*)(o0 + (size_t)r0 * DM + col)       = w0;
                *(float2*)(o0 + (size_t)(r0 + 8) * DM + col) = w1;
            }
        }
    }
}

// ---------------- HMMA flash attention -------------------------------------
// BQ=128 (8 warps x m16), BK=64. bf16 hi/lo split: QK 3 passes, PV 3 passes.
// Smem rows stride 144B (conflict-free ldmatrix: 36r mod 32 distinct).
#define BQ 128
#define BK 64
#define QSZ   (BQ*144)          // 18432 per Q part
#define KSZ   (BK*144)          // 9216 per KV part
#define KVBUF (4*KSZ)           // kh kl vh vl = 36864
#define ATT_SMEM (2*QSZ + 2*KVBUF)   // 110592

#define LOAD_KV(kb_, buf_) do {                                               \
    const uint32_t bb_ = KVs + (uint32_t)((buf_) * KVBUF);                    \
    _Pragma("unroll")                                                         \
    for (int i_ = 0; i_ < 8; ++i_) {                                          \
        int idx_ = i_ * 256 + tid;                                            \
        int part_ = idx_ >> 9, r_ = (idx_ >> 3) & 63, c_ = idx_ & 7;          \
        const __nv_bfloat16* src_ =                                           \
            ((part_ == 0) ? a_kh : (part_ == 1) ? a_kl :                      \
             (part_ == 2) ? a_vh : a_vl)                                      \
            + (rowb + (size_t)(kb_) * BK + r_) * DM + col0 + c_ * 8;          \
        cp_async16(bb_ + (uint32_t)(part_ * KSZ + r_ * 144 + c_ * 16), src_); \
    }                                                                         \
    CP_COMMIT();                                                              \
} while (0)

__global__ __launch_bounds__(256, 2)
void attn_hmma()
{
    extern __shared__ char smb[];
    const uint32_t sb   = smem_u32(smb);
    const uint32_t Qh_s = sb;
    const uint32_t Ql_s = sb + QSZ;
    const uint32_t KVs  = sb + 2 * QSZ;

    const int tid  = threadIdx.x;
    const int wid  = tid >> 5;
    const int lane = tid & 31;
    const int qi = blockIdx.x, h = blockIdx.y, b = blockIdx.z;
    const int col0 = h * DH;
    const size_t rowb = (size_t)b * SEQ;
    const int qbase = qi * BQ;
    const int m0w = wid * 16;
    const int nkb = 2 * qi + 2;

    const uint32_t ldsm_off =
        (uint32_t)(((lane & 7) + ((lane >> 3) & 1) * 8) * 144 + (lane >> 4) * 16);

    // stage Q (group), then KV0 (group)
#pragma unroll
    for (int i = 0; i < 8; ++i) {
        int idx = i * 256 + tid;
        int part = idx >> 10, r = (idx >> 3) & 127, c = idx & 7;
        const __nv_bfloat16* src = (part ? a_ql : a_qh)
            + (rowb + qbase + r) * DM + col0 + c * 8;
        cp_async16((part ? Ql_s : Qh_s) + (uint32_t)(r * 144 + c * 16), src);
    }
    CP_COMMIT();
    LOAD_KV(0, 0);

    float o[8][4];
#pragma unroll
    for (int ni = 0; ni < 8; ++ni)
#pragma unroll
        for (int c = 0; c < 4; ++c) o[ni][c] = 0.f;
    float m0r = -1e30f, m1r = -1e30f, l0r = 0.f, l1r = 0.f;

    const int grow0 = qbase + m0w + (lane >> 2);
    const int grow1 = grow0 + 8;

    for (int kb = 0; kb < nkb; ++kb) {
        if (kb + 1 < nkb) {
            LOAD_KV(kb + 1, (kb + 1) & 1);
            CP_WAIT1();
        } else {
            CP_WAIT0();
        }
        __syncthreads();

        const uint32_t bb  = KVs + (uint32_t)((kb & 1) * KVBUF);
        const uint32_t Khs = bb, Kls = bb + KSZ, Vhs = bb + 2*KSZ, Vls = bb + 3*KSZ;

        // ---- S = Q K^T, split x3 ----
        float s[8][4];
#pragma unroll
        for (int ni = 0; ni < 8; ++ni)
#pragma unroll
            for (int c = 0; c < 4; ++c) s[ni][c] = 0.f;

#pragma unroll
        for (int kk = 0; kk < 4; ++kk) {
            const uint32_t ko = (uint32_t)(kk * 32);
            uint32_t aqh[4], aql[4];
            ldsm4(aqh[0], aqh[1], aqh[2], aqh[3],
                  Qh_s + (uint32_t)(m0w * 144) + ko + ldsm_off);
            ldsm4(aql[0], aql[1], aql[2], aql[3],
                  Ql_s + (uint32_t)(m0w * 144) + ko + ldsm_off);
#pragma unroll
            for (int nj = 0; nj < 4; ++nj) {
                uint32_t bh[4], bl[4];
                ldsm4(bh[0], bh[1], bh[2], bh[3],
                      Khs + (uint32_t)(nj * 16 * 144) + ko + ldsm_off);
                ldsm4(bl[0], bl[1], bl[2], bl[3],
                      Kls + (uint32_t)(nj * 16 * 144) + ko + ldsm_off);
                mma16816(s[nj*2],   aqh, bh[0], bh[2]);
                mma16816(s[nj*2],   aqh, bl[0], bl[2]);
                mma16816(s[nj*2],   aql, bh[0], bh[2]);
                mma16816(s[nj*2+1], aqh, bh[1], bh[3]);
                mma16816(s[nj*2+1], aqh, bl[1], bl[3]);
                mma16816(s[nj*2+1], aql, bh[1], bh[3]);
            }
        }

        // ---- causal mask ----
        if (kb * 64 + 63 > grow0) {
#pragma unroll
            for (int ni = 0; ni < 8; ++ni) {
                const int gc = kb * 64 + ni * 8 + ((lane & 3) << 1);
                if (gc     > grow0) s[ni][0] = -1e30f;
                if (gc + 1 > grow0) s[ni][1] = -1e30f;
                if (gc     > grow1) s[ni][2] = -1e30f;
                if (gc + 1 > grow1) s[ni][3] = -1e30f;
            }
        }

        // ---- online softmax (rows grow0, grow1) ----
        float mx0 = -1e30f, mx1 = -1e30f;
#pragma unroll
        for (int ni = 0; ni < 8; ++ni) {
            mx0 = fmaxf(mx0, fmaxf(s[ni][0], s[ni][1]));
            mx1 = fmaxf(mx1, fmaxf(s[ni][2], s[ni][3]));
        }
        mx0 = fmaxf(mx0, __shfl_xor_sync(0xffffffffu, mx0, 1));
        mx0 = fmaxf(mx0, __shfl_xor_sync(0xffffffffu, mx0, 2));
        mx1 = fmaxf(mx1, __shfl_xor_sync(0xffffffffu, mx1, 1));
        mx1 = fmaxf(mx1, __shfl_xor_sync(0xffffffffu, mx1, 2));
        const float mn0 = fmaxf(m0r, mx0), mn1 = fmaxf(m1r, mx1);
        const float c0 = __expf(m0r - mn0), c1 = __expf(m1r - mn1);
        m0r = mn0; m1r = mn1;
        float rs0 = 0.f, rs1 = 0.f;
#pragma unroll
        for (int ni = 0; ni < 8; ++ni) {
            s[ni][0] = __expf(s[ni][0] - mn0); rs0 += s[ni][0];
            s[ni][1] = __expf(s[ni][1] - mn0); rs0 += s[ni][1];
            s[ni][2] = __expf(s[ni][2] - mn1); rs1 += s[ni][2];
            s[ni][3] = __expf(s[ni][3] - mn1); rs1 += s[ni][3];
        }
        rs0 += __shfl_xor_sync(0xffffffffu, rs0, 1);
        rs0 += __shfl_xor_sync(0xffffffffu, rs0, 2);
        rs1 += __shfl_xor_sync(0xffffffffu, rs1, 1);
        rs1 += __shfl_xor_sync(0xffffffffu, rs1, 2);
        l0r = l0r * c0 + rs0;
        l1r = l1r * c1 + rs1;
#pragma unroll
        for (int ni = 0; ni < 8; ++ni) {
            o[ni][0] *= c0; o[ni][1] *= c0;
            o[ni][2] *= c1; o[ni][3] *= c1;
        }

        // ---- O += P V, split x3 (drop pl*vl) ----
#pragma unroll
        for (int kt = 0; kt < 4; ++kt) {
            const int t0 = 2 * kt, t1 = 2 * kt + 1;
            uint32_t aph[4], apl[4];
            aph[0] = packbf(s[t0][0], s[t0][1]);
            aph[1] = packbf(s[t0][2], s[t0][3]);
            aph[2] = packbf(s[t1][0], s[t1][1]);
            aph[3] = packbf(s[t1][2], s[t1][3]);
            apl[0] = packresid(s[t0][0], s[t0][1], aph[0]);
            apl[1] = packresid(s[t0][2], s[t0][3], aph[1]);
            apl[2] = packresid(s[t1][0], s[t1][1], aph[2]);
            apl[3] = packresid(s[t1][2], s[t1][3], aph[3]);
#pragma unroll
            for (int dj = 0; dj < 4; ++dj) {
                uint32_t vh4[4], vl4[4];
                ldsm4t(vh4[0], vh4[1], vh4[2], vh4[3],
                       Vhs + (uint32_t)(kt * 16 * 144 + dj * 32) + ldsm_off);
                ldsm4t(vl4[0], vl4[1], vl4[2], vl4[3],
                       Vls + (uint32_t)(kt * 16 * 144 + dj * 32) + ldsm_off);
                mma16816(o[dj*2],   aph, vh4[0], vh4[1]);
                mma16816(o[dj*2],   aph, vl4[0], vl4[1]);
                mma16816(o[dj*2],   apl, vh4[0], vh4[1]);
                mma16816(o[dj*2+1], aph, vh4[2], vh4[3]);
                mma16816(o[dj*2+1], aph, vl4[2], vl4[3]);
                mma16816(o[dj*2+1], apl, vh4[2], vh4[3]);
            }
        }
        __syncthreads();   // buf safe before next prefetch overwrite
    }

    // ---- epilogue: z = O / l, split hi/lo to s_zh/s_zl ----
    const float i0 = 1.f / l0r, i1 = 1.f / l1r;
#pragma unroll
    for (int ni = 0; ni < 8; ++ni) {
        const size_t base0 = (rowb + grow0) * DM + col0 + ni * 8 + ((lane & 3) << 1);
        split_store(s_zh, s_zl, base0,            o[ni][0] * i0, o[ni][1] * i0);
        split_store(s_zh, s_zl, base0 + 8 * DM,   o[ni][2] * i1, o[ni][3] * i1);
    }
}

// ---------------------------------------------------------------------------
extern "C" void kernel_launch(void* const* d_in, const int* in_sizes, int n_in,
                              void* d_out, int out_size)
{
    const float* x  = (const float*)d_in[0];
    const float* Wq = (const float*)d_in[1];
    const float* Wk = (const float*)d_in[2];
    const float* Wv = (const float*)d_in[3];
    const float* Wo = (const float*)d_in[4];
    const float* bq = (const float*)d_in[5];
    const float* bk = (const float*)d_in[6];
    const float* bv = (const float*)d_in[7];
    const float* bo = (const float*)d_in[8];
    float* out = (float*)d_out;

    cudaFuncSetAttribute(hmma_gemm,
                         cudaFuncAttributeMaxDynamicSharedMemorySize, SMEM_HM);
    cudaFuncSetAttribute(attn_hmma,
                         cudaFuncAttributeMaxDynamicSharedMemorySize, ATT_SMEM);

    split_plain<<<(MTOT*DM)/(256*4), 256>>>(x);
    transpose_split<<<dim3(16, 1, 16), 256>>>(Wq, 0, DM, DH);
    transpose_split<<<dim3(16, 1, 16), 256>>>(Wk, 1, DM, DH);
    transpose_split<<<dim3(16, 1, 16), 256>>>(Wv, 2, DM, DH);
    transpose_split<<<dim3(16, 16, 1), 256>>>(Wo, 3, DM, DM);

    hmma_gemm<<<dim3(24, 32), 256, SMEM_HM>>>(1, nullptr, bq, bk, bv);

    attn_hmma<<<dim3(SEQ / BQ, NH, NB), 256, ATT_SMEM>>>();

    hmma_gemm<<<dim3(8, 32), 256, SMEM_HM>>>(0, out, bo, nullptr, nullptr);
}